// round 17
// baseline (speedup 1.0000x reference)
#include <cuda_runtime.h>
#include <cuda_fp16.h>
#include <math.h>
#include <stdint.h>

#define BB 4
#define LL 2048
#define SS 2048
#define HH 8
#define EE 64
#define HE 512          // HH*EE
#define BH 32           // BB*HH
#define NELEM (BB*LL*HH*EE)
#define NROWS (BH * LL)
#define EPSF 1e-6f
#define SCALEF 0.125f   // 1/sqrt(64)
#define NSP 8           // gram s-partitions

// -------- device scratch (alloc-free rule: __device__ globals) --------
__device__ __half g_qth[NELEM];                    // fp16 transformed Q (8 MB)
__device__ __half g_kth[NELEM];                    // fp16 transformed K
__device__ __half g_vt[(size_t)BH * EE * SS];      // fp16 V transposed [bh][d][s] (8 MB)
__device__ float  g_gramp[(size_t)BH * NSP * 64 * 64]; // partial Gram (4 MB)
__device__ float  g_ksump[(size_t)BH * NSP * 64];
__device__ float2 g_alsh[NROWS];                   // per row: (alpha, shift)

__device__ __forceinline__ void mma16(float* c, const uint32_t* a, const uint32_t* b) {
    asm volatile("mma.sync.aligned.m16n8k16.row.col.f32.f16.f16.f32 "
                 "{%0,%1,%2,%3},{%4,%5,%6,%7},{%8,%9},{%0,%1,%2,%3};"
                 : "+f"(c[0]), "+f"(c[1]), "+f"(c[2]), "+f"(c[3])
                 : "r"(a[0]), "r"(a[1]), "r"(a[2]), "r"(a[3]), "r"(b[0]), "r"(b[1]));
}

__device__ __forceinline__ void cpasync16(uint32_t dst, const void* src) {
    asm volatile("cp.async.cg.shared.global [%0], [%1], 16;" :: "r"(dst), "l"(src));
}
__device__ __forceinline__ void cp_commit() { asm volatile("cp.async.commit_group;"); }
template<int N> __device__ __forceinline__ void cp_wait() {
    asm volatile("cp.async.wait_group %0;" :: "n"(N));
}
__device__ __forceinline__ uint32_t h2u(__half2 h) { return *reinterpret_cast<uint32_t*>(&h); }

// ==================== kernel 1: transform; std over HEADS (axis=-2), fp16 out ====================
__global__ void __launch_bounds__(512) k_transform(const float* __restrict__ q,
                                                   const float* __restrict__ k,
                                                   const float* __restrict__ dw,
                                                   const float* __restrict__ dp) {
    int sel = blockIdx.y;
    const float* x = (sel ? k : q) + (size_t)blockIdx.x * HE;
    __half* o = (sel ? g_kth : g_qth) + (size_t)blockIdx.x * HE;
    float w = dw[0];
    float p = dp[0];
    int tid = threadIdx.x;          // h*64 + e
    int e = tid & 63;
    float v = x[tid];

    __shared__ float s1[512];
    __shared__ float istd[64];
    s1[tid] = v;
    __syncthreads();
    if (tid < 64) {
        float s = 0.f, ss = 0.f;
        #pragma unroll
        for (int h = 0; h < 8; h++) {
            float u = s1[h * 64 + tid];
            s += u; ss += u * u;
        }
        float mean = s * 0.125f;
        float var = (ss - s * mean) * (1.0f / 7.0f);    // unbiased n=8
        istd[tid] = 1.0f / (sqrtf(fmaxf(var, 0.f)) + EPSF);
    }
    __syncthreads();
    o[tid] = __float2half_rn(tanhf(v * istd[e] * w) * p);
}

// ==================== kernel 1b: V -> fp16 transposed [bh][d][s] ====================
__global__ void __launch_bounds__(256) k_vconv(const float* __restrict__ V) {
    __shared__ float t[64][65];
    int bh = blockIdx.y, b = bh >> 3, h = bh & 7;
    int s0 = blockIdx.x * 64;
    const float* src = V + ((size_t)b * SS + s0) * HE + h * EE;
    int tid = threadIdx.x;
    #pragma unroll
    for (int p = 0; p < 4; p++) {
        int idx = tid + p * 256;
        int s = idx >> 4, e4 = (idx & 15) * 4;
        float4 v = *(const float4*)(src + (size_t)s * HE + e4);
        t[s][e4] = v.x; t[s][e4 + 1] = v.y; t[s][e4 + 2] = v.z; t[s][e4 + 3] = v.w;
    }
    __syncthreads();
    __half* dst = g_vt + (size_t)bh * EE * SS + s0;
    {
        int e = tid >> 2, sb = (tid & 3) * 16;
        __half2 o8[8];
        #pragma unroll
        for (int j = 0; j < 8; j++)
            o8[j] = __floats2half2_rn(t[sb + 2 * j][e], t[sb + 2 * j + 1][e]);
        *(uint4*)(dst + (size_t)e * SS + sb)     = *(uint4*)&o8[0];
        *(uint4*)(dst + (size_t)e * SS + sb + 8) = *(uint4*)&o8[4];
    }
}

// ==================== kernel 2: partial Gram G = K^T K and ksum, per (bh, s-slice) ====================
__global__ void __launch_bounds__(256) k_gram() {
    __shared__ float tile[32][64];
    int sp = blockIdx.x, bh = blockIdx.y;
    int b = bh >> 3, h = bh & 7;
    const __half* K = g_kth + (size_t)b * LL * HE + h * EE;
    int tid = threadIdx.x;
    int e = tid >> 2, fb = (tid & 3) * 16;
    int lr = tid >> 3, lc = (tid & 7) * 8;

    float gacc[16] = {};
    float ksacc = 0.f;
    for (int blk = 0; blk < 8; blk++) {
        int s0 = sp * 256 + blk * 32;
        {
            uint4 raw = *(const uint4*)(K + (size_t)(s0 + lr) * HE + lc);
            __half2* hp = (__half2*)&raw;
            #pragma unroll
            for (int j = 0; j < 4; j++) {
                float2 f = __half22float2(hp[j]);
                tile[lr][lc + 2 * j] = f.x;
                tile[lr][lc + 2 * j + 1] = f.y;
            }
        }
        __syncthreads();
        for (int s = 0; s < 32; s++) {
            float ke = tile[s][e];
            if ((tid & 3) == 0) ksacc += ke;
            #pragma unroll
            for (int j = 0; j < 16; j++)
                gacc[j] += ke * tile[s][fb + j];
        }
        __syncthreads();
    }
    float* gp = g_gramp + ((size_t)bh * NSP + sp) * 4096;
    #pragma unroll
    for (int j = 0; j < 16; j++)
        gp[e * 64 + fb + j] = gacc[j];
    if ((tid & 3) == 0)
        g_ksump[((size_t)bh * NSP + sp) * 64 + e] = ksacc;
}

// ==================== kernel 3: per-row alpha/shift from Gram (hoisted q->float) ====================
__global__ void __launch_bounds__(256) k_alpha2() {
    __shared__ float sG[4096];
    __shared__ float sks[64];
    int bh = blockIdx.x >> 3;
    int l0 = (blockIdx.x & 7) * 256;
    int b = bh >> 3, h = bh & 7;
    int tid = threadIdx.x;

    #pragma unroll
    for (int j = 0; j < 16; j++) {
        int idx = j * 256 + tid;
        float a = 0.f;
        #pragma unroll
        for (int p = 0; p < NSP; p++)
            a += g_gramp[((size_t)bh * NSP + p) * 4096 + idx];
        sG[idx] = a;
    }
    if (tid < 64) {
        float a = 0.f;
        #pragma unroll
        for (int p = 0; p < NSP; p++)
            a += g_ksump[((size_t)bh * NSP + p) * 64 + tid];
        sks[tid] = a;
    }
    __syncthreads();

    int l = l0 + tid;
    const __half* qr = g_qth + ((size_t)(b * LL + l) * HH + h) * EE;
    float qf[64];
    #pragma unroll
    for (int j = 0; j < 8; j++) {
        uint4 raw = *(const uint4*)(qr + j * 8);
        const __half2* hp = (const __half2*)&raw;
        #pragma unroll
        for (int u = 0; u < 4; u++) {
            float2 f = __half22float2(hp[u]);
            qf[j * 8 + 2 * u] = f.x;
            qf[j * 8 + 2 * u + 1] = f.y;
        }
    }

    float s1 = 0.f, s2 = 0.f;
    #pragma unroll 8
    for (int e = 0; e < 64; e++) {
        float qe = qf[e];
        s1 += qe * sks[e];
        const float* Ge = sG + e * 64;
        float t = 0.f;
        #pragma unroll
        for (int f = 0; f < 64; f++)
            t += Ge[f] * qf[f];
        s2 += qe * t;
    }
    float mean = s1 * (1.0f / (float)SS);
    float var = (s2 - s1 * mean) * (1.0f / (float)(SS - 1));   // unbiased
    float tau = sqrtf(fmaxf(var, 0.f) + EPSF);
    float alpha = SCALEF / tau;
    g_alsh[(size_t)bh * LL + l] = make_float2(alpha, alpha * mean);
}

// ==================== kernel 4: fused flash, s-chunk 64, pair-pipelined ====================
#define QPADH 72                       // halfs per Q/K row (144 B, 16B-aligned, conflict-free)
#define QTILE (128 * QPADH)            // 9216 halfs
#define KST (64 * QPADH)               // 4608 halfs per K stage
#define VPADH 72                       // halfs per V row (64 s + pad)
#define VST (64 * VPADH)               // 4608 halfs per V stage
#define FNST 3
#define FSMEM ((QTILE + FNST * (KST + VST)) * 2)   // 73728 B

__global__ void __launch_bounds__(256, 2) k_flash(float* __restrict__ O) {
    extern __shared__ __half sh[];
    __half* Qs  = sh;                         // [128][QPADH]
    __half* Ksb = sh + QTILE;                 // [FNST][64][QPADH]
    __half* Vsb = sh + QTILE + FNST * KST;    // [FNST][64][VPADH]
    int l0 = blockIdx.x << 7;
    int bh = blockIdx.y;
    int b = bh >> 3, h = bh & 7;
    const __half* Qg = g_qth + ((size_t)(b * LL + l0)) * HE + h * EE;
    const __half* Kg = g_kth + (size_t)b * LL * HE + h * EE;
    const __half* Vt = g_vt + (size_t)bh * EE * SS;
    int tid = threadIdx.x;

    uint32_t qsb = (uint32_t)__cvta_generic_to_shared(Qs);
    uint32_t ksb = (uint32_t)__cvta_generic_to_shared(Ksb);
    uint32_t vsb = (uint32_t)__cvta_generic_to_shared(Vsb);

    // ---- issue Q tile (128 rows x 64 halfs): 2 threads/row, 4x16B each ----
    {
        int qr = tid >> 1, qc = (tid & 1) * 32;
        #pragma unroll
        for (int j = 0; j < 4; j++)
            cpasync16(qsb + (uint32_t)(qr * QPADH + qc + j * 8) * 2,
                      Qg + (size_t)qr * HE + qc + j * 8);
        cp_commit();
    }

    int kfr = tid >> 2, kfc = (tid & 3) * 16;   // K fill: 64 rows x 64 halfs, 2x16B/thread
    int vfr = tid >> 2, vfc = (tid & 3) * 16;   // V fill: 64 d-rows x 64 s-halfs, 2x16B/thread

#define ISSUEF(tt, buf)                                                               \
    do {                                                                              \
        cpasync16(ksb + (uint32_t)((buf) * KST + kfr * QPADH + kfc) * 2,              \
                  Kg + (size_t)((tt) * 64 + kfr) * HE + kfc);                         \
        cpasync16(ksb + (uint32_t)((buf) * KST + kfr * QPADH + kfc + 8) * 2,          \
                  Kg + (size_t)((tt) * 64 + kfr) * HE + kfc + 8);                     \
        cpasync16(vsb + (uint32_t)((buf) * VST + vfr * VPADH + vfc) * 2,              \
                  Vt + (size_t)vfr * SS + (tt) * 64 + vfc);                           \
        cpasync16(vsb + (uint32_t)((buf) * VST + vfr * VPADH + vfc + 8) * 2,          \
                  Vt + (size_t)vfr * SS + (tt) * 64 + vfc + 8);                       \
    } while (0)

    ISSUEF(0, 0); cp_commit();
    ISSUEF(1, 1); cp_commit();

    int lane = tid & 31, wid = tid >> 5;
    int wr = wid * 16;
    int g = lane >> 2, t4 = lane & 3;

    float2 v0 = g_alsh[(size_t)bh * LL + l0 + wr + g];
    float2 v1 = g_alsh[(size_t)bh * LL + l0 + wr + g + 8];
    float al0 = v0.x, sh0 = v0.y, al1 = v1.x, sh1 = v1.y;

    // ---- Q fragments to registers (after Q group drains) ----
    cp_wait<2>();
    __syncthreads();
    uint32_t qa[4][4];
    #pragma unroll
    for (int ks = 0; ks < 4; ks++) {
        const __half* p = Qs + (wr + g) * QPADH + ks * 16 + 2 * t4;
        qa[ks][0] = *(const uint32_t*)p;
        qa[ks][1] = *(const uint32_t*)(p + 8 * QPADH);
        qa[ks][2] = *(const uint32_t*)(p + 8);
        qa[ks][3] = *(const uint32_t*)(p + 8 * QPADH + 8);
    }

    float acc[8][4];
    #pragma unroll
    for (int j = 0; j < 8; j++)
        #pragma unroll
        for (int r = 0; r < 4; r++) acc[j][r] = 0.f;
    float esum0 = 0.f, esum1 = 0.f;

    for (int tt = 0; tt < 32; tt++) {
        int buf = tt % FNST;
        if (tt + 2 < 32) { ISSUEF(tt + 2, (tt + 2) % FNST); cp_commit(); cp_wait<2>(); }
        else if (tt + 1 < 32) { cp_wait<1>(); }
        else { cp_wait<0>(); }
        __syncthreads();

        const __half* Kb = Ksb + buf * KST;
        const __half* Vf = Vsb + buf * VST;

        // process s-columns in 16-wide pairs: MMA1-pair -> exp -> pack -> MMA2 row
        #pragma unroll
        for (int pr = 0; pr < 4; pr++) {
            float s0a[4] = {0.f, 0.f, 0.f, 0.f};
            float s1a[4] = {0.f, 0.f, 0.f, 0.f};
            #pragma unroll
            for (int ks = 0; ks < 4; ks++) {
                const __half* p0 = Kb + (pr * 16 + g) * QPADH + ks * 16 + 2 * t4;
                uint32_t bf0[2], bf1[2];
                bf0[0] = *(const uint32_t*)p0;
                bf0[1] = *(const uint32_t*)(p0 + 8);
                bf1[0] = *(const uint32_t*)(p0 + 8 * QPADH);
                bf1[1] = *(const uint32_t*)(p0 + 8 * QPADH + 8);
                mma16(s0a, qa[ks], bf0);
                mma16(s1a, qa[ks], bf1);
            }
            float e00 = __expf(fmaf(al0, s0a[0], -sh0));
            float e01 = __expf(fmaf(al0, s0a[1], -sh0));
            float e02 = __expf(fmaf(al1, s0a[2], -sh1));
            float e03 = __expf(fmaf(al1, s0a[3], -sh1));
            float e10 = __expf(fmaf(al0, s1a[0], -sh0));
            float e11 = __expf(fmaf(al0, s1a[1], -sh0));
            float e12 = __expf(fmaf(al1, s1a[2], -sh1));
            float e13 = __expf(fmaf(al1, s1a[3], -sh1));
            esum0 += e00 + e01 + e10 + e11;
            esum1 += e02 + e03 + e12 + e13;
            uint32_t pa[4];
            pa[0] = h2u(__floats2half2_rn(e00, e01));
            pa[1] = h2u(__floats2half2_rn(e02, e03));
            pa[2] = h2u(__floats2half2_rn(e10, e11));
            pa[3] = h2u(__floats2half2_rn(e12, e13));
            #pragma unroll
            for (int nj = 0; nj < 8; nj++) {
                const __half* pv = Vf + (nj * 8 + g) * VPADH + pr * 16 + 2 * t4;
                uint32_t bf[2];
                bf[0] = *(const uint32_t*)pv;
                bf[1] = *(const uint32_t*)(pv + 8);
                mma16(acc[nj], pa, bf);
            }
        }
        __syncthreads();
    }
#undef ISSUEF

    // expsum quad-butterfly
    esum0 += __shfl_xor_sync(0xffffffffu, esum0, 1);
    esum0 += __shfl_xor_sync(0xffffffffu, esum0, 2);
    esum1 += __shfl_xor_sync(0xffffffffu, esum1, 1);
    esum1 += __shfl_xor_sync(0xffffffffu, esum1, 2);
    float inv0 = 1.0f / esum0;
    float inv1 = 1.0f / esum1;

    int r0 = l0 + wr + g;
    #pragma unroll
    for (int nj = 0; nj < 8; nj++) {
        int d = nj * 8 + 2 * t4;
        size_t o0 = ((size_t)((size_t)b * LL + r0) * HH + h) * EE + d;
        *(float2*)&O[o0] = make_float2(acc[nj][0] * inv0, acc[nj][1] * inv0);
        size_t o1 = ((size_t)((size_t)b * LL + r0 + 8) * HH + h) * EE + d;
        *(float2*)&O[o1] = make_float2(acc[nj][2] * inv1, acc[nj][3] * inv1);
    }
}

// ==================== launch ====================
extern "C" void kernel_launch(void* const* d_in, const int* in_sizes, int n_in,
                              void* d_out, int out_size) {
    const float* q  = (const float*)d_in[0];
    const float* k  = (const float*)d_in[1];
    const float* v  = (const float*)d_in[2];
    const float* dw = (const float*)d_in[4];
    const float* dp = (const float*)d_in[5];
    float* out = (float*)d_out;

    cudaFuncSetAttribute(k_flash, cudaFuncAttributeMaxDynamicSharedMemorySize, FSMEM);

    k_transform<<<dim3(BB * LL, 2), 512>>>(q, k, dw, dp);
    k_vconv    <<<dim3(SS / 64, BH), 256>>>(v);
    k_gram     <<<dim3(NSP, BH), 256>>>();
    k_alpha2   <<<NROWS / 256, 256>>>();
    k_flash    <<<dim3(LL / 128, BH), 256, FSMEM>>>(out);
}